// round 8
// baseline (speedup 1.0000x reference)
#include <cuda_runtime.h>
#include <math_constants.h>
#include <cstdint>

#define BATCH 16
#define SEQ   4096
#define RANKS 8
#define PER   512
#define NTC   512

// Deterministic per-slot scratch (zero-init at module load; counter self-resets).
__device__ float g_sum_s[BATCH][RANKS];
__device__ float g_sum_e[BATCH][RANKS];
__device__ float g_wsv[BATCH][RANKS];
__device__ int   g_wsi[BATCH][RANKS];
__device__ float g_wev[BATCH][RANKS];
__device__ int   g_wei[BATCH][RANKS];
__device__ int   g_arrive[BATCH * 32];   // stride 32 ints = 128B: no L2 slot sharing

__global__ __launch_bounds__(NTC, 1)
void pred_head(const float* __restrict__ start_logits,
               const float* __restrict__ end_logits,
               float* __restrict__ out) {
    // pfx_e[0..511]: per-warp prefix-max of exp(end); [512..541]: next-chunk halo prefix
    // sfx_s[32..543]: per-warp suffix-max of exp(start); [2..31]: prev-chunk halo suffix
    __shared__ float pfx_e[544];
    __shared__ float sfx_s[544];
    __shared__ float red[16], red2[16];
    __shared__ float wav[16], wav2[16];
    __shared__ int   wai[16], wai2[16];
    __shared__ int   lastflag;

    const int t    = threadIdx.x;
    const int lane = t & 31;
    const int wid  = t >> 5;
    const int row  = blockIdx.x >> 3;
    const int rank = blockIdx.x & (RANKS - 1);
    const int col  = rank * PER + t;
    const float* srow = start_logits + row * SEQ;
    const float* erow = end_logits   + row * SEQ;

    // ---- own loads + exp; raw exps go straight to out (rescaled later by last CTA) ----
    const float sv = __expf(srow[col]);
    const float ev = __expf(erow[col]);
    out[row * SEQ + col]               = sv;
    out[BATCH * SEQ + row * SEQ + col] = ev;

    // ---- halo recompute from gmem (no cross-CTA exchange) ----
    if (wid == 1 && lane < 30) {
        // prev chunk elems [rank*PER-30+lane .. rank*PER-1]: suffix-max of exp(start)
        float hv = (rank > 0) ? __expf(srow[rank * PER - 30 + lane]) : 0.f;
        #pragma unroll
        for (int o = 1; o < 32; o <<= 1) {
            float b = __shfl_down_sync(0x3fffffffu, hv, o);
            if (lane + o < 30) hv = fmaxf(hv, b);
        }
        sfx_s[2 + lane] = hv;
    }
    if (wid == 2 && lane < 30) {
        // next chunk elems [(rank+1)*PER .. +lane]: prefix-max of exp(end)
        float hv = (rank < RANKS - 1) ? __expf(erow[(rank + 1) * PER + lane]) : 0.f;
        #pragma unroll
        for (int o = 1; o < 32; o <<= 1) {
            float a = __shfl_up_sync(0x3fffffffu, hv, o);
            if (lane >= o) hv = fmaxf(hv, a);
        }
        pfx_e[512 + lane] = hv;
    }

    // ---- per-warp prefix/suffix maxima (own chunk) ----
    float pe = ev, se_ = ev;   // prefix/suffix of exp(end)
    float ps_ = sv, ssx = sv;  // prefix/suffix of exp(start)
    #pragma unroll
    for (int o = 1; o < 32; o <<= 1) {
        float a = __shfl_up_sync(0xffffffffu, pe, o);    if (lane >= o)     pe  = fmaxf(pe, a);
        float b = __shfl_down_sync(0xffffffffu, se_, o); if (lane + o < 32) se_ = fmaxf(se_, b);
        float c = __shfl_up_sync(0xffffffffu, ps_, o);   if (lane >= o)     ps_ = fmaxf(ps_, c);
        float d = __shfl_down_sync(0xffffffffu, ssx, o); if (lane + o < 32) ssx = fmaxf(ssx, d);
    }
    pfx_e[t] = pe;
    sfx_s[32 + t] = ssx;

    // ---- per-warp partial sums ----
    float a = sv, c = ev;
    #pragma unroll
    for (int o = 16; o; o >>= 1) {
        a += __shfl_xor_sync(0xffffffffu, a, o);
        c += __shfl_xor_sync(0xffffffffu, c, o);
    }
    if (lane == 0) { red[wid] = a; red2[wid] = c; }

    __syncthreads();   // #1: prefix/suffix + halos + partials visible CTA-wide

    // ---- width-31 windows via prefix/suffix decomposition ----
    // F[i] = max exp(end)[i..i+30]; B[j] = max exp(start)[j-30..j]
    const float pe30 = __shfl_sync(0xffffffffu, pe, 30);
    const float ss1  = __shfl_sync(0xffffffffu, ssx, 1);
    float F, Bv;
    if (lane == 0)       F = pe30;
    else if (lane == 1)  F = se_;
    else                 F = fmaxf(se_, pfx_e[t + 30]);
    if (lane == 31)      Bv = ss1;
    else if (lane == 30) Bv = ps_;
    else                 Bv = fmaxf(ps_, sfx_s[t + 2]);

    // ---- scores + warp argmax (dual, first-index tie-break) ----
    float bsv = sv * F;  int bsi = col;
    float bev = ev * Bv; int bei = col;
    #pragma unroll
    for (int o = 16; o; o >>= 1) {
        float ov = __shfl_xor_sync(0xffffffffu, bsv, o);
        int   oi = __shfl_xor_sync(0xffffffffu, bsi, o);
        if (ov > bsv || (ov == bsv && oi < bsi)) { bsv = ov; bsi = oi; }
        float ov2 = __shfl_xor_sync(0xffffffffu, bev, o);
        int   oi2 = __shfl_xor_sync(0xffffffffu, bei, o);
        if (ov2 > bev || (ov2 == bev && oi2 < bei)) { bev = ov2; bei = oi2; }
    }
    if (lane == 0) { wav[wid] = bsv; wai[wid] = bsi; wav2[wid] = bev; wai2[wid] = bei; }

    __syncthreads();   // #2: warp partials visible

    // ---- CTA-level results -> gmem scratch (fixed slots; deterministic) ----
    if (wid == 0) {
        float aa = (lane < 16) ? red[lane]  : 0.f;
        float cc = (lane < 16) ? red2[lane] : 0.f;
        #pragma unroll
        for (int o = 8; o; o >>= 1) {
            aa += __shfl_xor_sync(0xffffffffu, aa, o);
            cc += __shfl_xor_sync(0xffffffffu, cc, o);
        }
        if (lane == 0) { g_sum_s[row][rank] = aa; g_sum_e[row][rank] = cc; __threadfence(); }
    } else if (wid == 1) {
        float v1 = (lane < 16) ? wav[lane] : -CUDART_INF_F;
        int   i1 = (lane < 16) ? wai[lane] : 0x7fffffff;
        #pragma unroll
        for (int o = 8; o; o >>= 1) {
            float ov = __shfl_xor_sync(0xffffffffu, v1, o);
            int   oi = __shfl_xor_sync(0xffffffffu, i1, o);
            if (ov > v1 || (ov == v1 && oi < i1)) { v1 = ov; i1 = oi; }
        }
        if (lane == 0) { g_wsv[row][rank] = v1; g_wsi[row][rank] = i1; __threadfence(); }
    } else if (wid == 2) {
        float v2 = (lane < 16) ? wav2[lane] : -CUDART_INF_F;
        int   i2 = (lane < 16) ? wai2[lane] : 0x7fffffff;
        #pragma unroll
        for (int o = 8; o; o >>= 1) {
            float ov = __shfl_xor_sync(0xffffffffu, v2, o);
            int   oi = __shfl_xor_sync(0xffffffffu, i2, o);
            if (ov > v2 || (ov == v2 && oi < i2)) { v2 = ov; i2 = oi; }
        }
        if (lane == 0) { g_wev[row][rank] = v2; g_wei[row][rank] = i2; __threadfence(); }
    }
    // raw-exp STGs from all threads must also be fenced before arrival
    __threadfence();
    __syncthreads();   // #3: all stores + fences done before the arrival atomic

    if (t == 0) {
        int old = atomicAdd(&g_arrive[row * 32], 1);
        lastflag = (old == RANKS - 1);
    }
    __syncthreads();   // #4
    if (!lastflag) return;          // 7 of 8 CTAs exit with zero waiting

    // ================= last CTA of this row: tail =================
    if (t == 0) g_arrive[row * 32] = 0;   // self-restore for next replay
    __threadfence();                       // acquire side

    // ---- in-order (deterministic) global sums; every warp redundantly ----
    float v = (lane < 8) ? g_sum_s[row][lane] : ((lane < 16) ? g_sum_e[row][lane - 8] : 0.f);
    v += __shfl_xor_sync(0xffffffffu, v, 4);
    v += __shfl_xor_sync(0xffffffffu, v, 2);
    v += __shfl_xor_sync(0xffffffffu, v, 1);
    const float inv_s = __frcp_rn(__shfl_sync(0xffffffffu, v, 0));
    const float inv_e = __frcp_rn(__shfl_sync(0xffffffffu, v, 8));

    // ---- rescale the whole row in place (L2-hot, float4) ----
    float4* o4s = (float4*)(out + row * SEQ);
    float4* o4e = (float4*)(out + BATCH * SEQ + row * SEQ);
    #pragma unroll
    for (int k = 0; k < 2; k++) {
        int i = t + k * NTC;                    // 1024 float4 per array
        float4 x = o4s[i];
        x.x *= inv_s; x.y *= inv_s; x.z *= inv_s; x.w *= inv_s;
        o4s[i] = x;
        float4 y = o4e[i];
        y.x *= inv_e; y.y *= inv_e; y.z *= inv_e; y.w *= inv_e;
        o4e[i] = y;
    }

    // ---- winner reduction in rank order (deterministic) ----
    if (wid == 0) {
        float v1 = (lane < 8) ? g_wsv[row][lane] : -CUDART_INF_F;
        int   i1 = (lane < 8) ? g_wsi[row][lane] : 0x7fffffff;
        float v2 = (lane < 8) ? g_wev[row][lane] : -CUDART_INF_F;
        int   i2 = (lane < 8) ? g_wei[row][lane] : 0x7fffffff;
        #pragma unroll
        for (int o = 4; o; o >>= 1) {
            float ov = __shfl_xor_sync(0xffffffffu, v1, o);
            int   oi = __shfl_xor_sync(0xffffffffu, i1, o);
            if (ov > v1 || (ov == v1 && oi < i1)) { v1 = ov; i1 = oi; }
            float ov2 = __shfl_xor_sync(0xffffffffu, v2, o);
            int   oi2 = __shfl_xor_sync(0xffffffffu, i2, o);
            if (ov2 > v2 || (ov2 == v2 && oi2 < i2)) { v2 = ov2; i2 = oi2; }
        }
        if (lane == 0) {
            out[2 * BATCH * SEQ + row]         = (float)i1;
            out[2 * BATCH * SEQ + BATCH + row] = (float)i2;
        }
    }
}

extern "C" void kernel_launch(void* const* d_in, const int* in_sizes, int n_in,
                              void* d_out, int out_size) {
    const float* start_logits = (const float*)d_in[0];
    const float* end_logits   = (const float*)d_in[1];
    float* out = (float*)d_out;
    pred_head<<<BATCH * RANKS, NTC>>>(start_logits, end_logits, out);
}

// round 9
// speedup vs baseline: 1.3014x; 1.3014x over previous
#include <cuda_runtime.h>
#include <math_constants.h>
#include <cstdint>

#define BATCH 16
#define SEQ   4096
#define RANKS 8
#define PER   512
#define NTC   512

__device__ __forceinline__ void st_remote_f32(float* lp, unsigned int r, float v) {
    unsigned int la = (unsigned int)__cvta_generic_to_shared((void*)lp);
    unsigned int ra;
    asm("mapa.shared::cluster.u32 %0, %1, %2;" : "=r"(ra) : "r"(la), "r"(r));
    asm volatile("st.shared::cluster.f32 [%0], %1;" :: "r"(ra), "f"(v) : "memory");
}
__device__ __forceinline__ void st_remote_s32(int* lp, unsigned int r, int v) {
    unsigned int la = (unsigned int)__cvta_generic_to_shared((void*)lp);
    unsigned int ra;
    asm("mapa.shared::cluster.u32 %0, %1, %2;" : "=r"(ra) : "r"(la), "r"(r));
    asm volatile("st.shared::cluster.b32 [%0], %1;" :: "r"(ra), "r"(v) : "memory");
}
#define CLUSTER_SYNC() do { \
    asm volatile("barrier.cluster.arrive.aligned;" ::: "memory"); \
    asm volatile("barrier.cluster.wait.aligned;"   ::: "memory"); } while (0)

__global__ __launch_bounds__(NTC, 1) __cluster_dims__(RANKS, 1, 1)
void pred_head_cluster(const float* __restrict__ start_logits,
                       const float* __restrict__ end_logits,
                       float* __restrict__ out) {
    // LOG-SPACE windows: all scans on raw logits (argmax invariant under exp).
    // pfx_e[0..511]: per-warp prefix-max of end-logit; [512..541]: next-chunk halo prefix
    // sfx_s[32..543]: per-warp suffix-max of start-logit; [2..31]: prev-chunk halo suffix
    __shared__ float pfx_e[544];
    __shared__ float sfx_s[544];
    __shared__ float red[16], red2[16];
    __shared__ float wav[16], wav2[16];
    __shared__ int   wai[16], wai2[16];
    __shared__ float s_parts[RANKS], e_parts[RANKS];
    __shared__ float wsv[RANKS], wev[RANKS];
    __shared__ int   wsi[RANKS], wei[RANKS];

    const int t = threadIdx.x;
    const int lane = t & 31;
    const int wid  = t >> 5;
    unsigned int rank;
    asm("mov.u32 %0, %%cluster_ctarank;" : "=r"(rank));
    const int row = blockIdx.x >> 3;
    const int col = (int)rank * PER + t;
    const float* srow = start_logits + row * SEQ;
    const float* erow = end_logits   + row * SEQ;

    // ---- own logit loads (argmax path starts here, no exp in front) ----
    const float sl = srow[col];
    const float el = erow[col];

    // ---- halo: raw logit max-scans (no exp needed in log space) ----
    if (wid == 1 && lane < 30) {
        // prev chunk [rank*PER-30+lane .. rank*PER-1]: suffix-max of start-logit
        float hv = (rank > 0) ? srow[(int)rank * PER - 30 + lane] : -CUDART_INF_F;
        #pragma unroll
        for (int o = 1; o < 32; o <<= 1) {
            float b = __shfl_down_sync(0x3fffffffu, hv, o);
            if (lane + o < 30) hv = fmaxf(hv, b);
        }
        sfx_s[2 + lane] = hv;
    }
    if (wid == 2 && lane < 30) {
        // next chunk [(rank+1)*PER .. +lane]: prefix-max of end-logit
        float hv = (rank < RANKS - 1) ? erow[((int)rank + 1) * PER + lane] : -CUDART_INF_F;
        #pragma unroll
        for (int o = 1; o < 32; o <<= 1) {
            float a = __shfl_up_sync(0x3fffffffu, hv, o);
            if (lane >= o) hv = fmaxf(hv, a);
        }
        pfx_e[512 + lane] = hv;
    }

    // ---- per-warp prefix/suffix maxima on logits ----
    float pe = el, se_ = el;   // prefix/suffix of end-logit
    float ps_ = sl, ssx = sl;  // prefix/suffix of start-logit
    #pragma unroll
    for (int o = 1; o < 32; o <<= 1) {
        float a = __shfl_up_sync(0xffffffffu, pe, o);    if (lane >= o)     pe  = fmaxf(pe, a);
        float b = __shfl_down_sync(0xffffffffu, se_, o); if (lane + o < 32) se_ = fmaxf(se_, b);
        float c = __shfl_up_sync(0xffffffffu, ps_, o);   if (lane >= o)     ps_ = fmaxf(ps_, c);
        float d = __shfl_down_sync(0xffffffffu, ssx, o); if (lane + o < 32) ssx = fmaxf(ssx, d);
    }
    pfx_e[t] = pe;
    sfx_s[32 + t] = ssx;

    // ---- exps (MUFU) — needed only for probs/sums; overlaps the scan pipe ----
    const float sv = __expf(sl);
    const float ev = __expf(el);

    // ---- per-warp partial sums ----
    float a = sv, c = ev;
    #pragma unroll
    for (int o = 16; o; o >>= 1) {
        a += __shfl_xor_sync(0xffffffffu, a, o);
        c += __shfl_xor_sync(0xffffffffu, c, o);
    }
    if (lane == 0) { red[wid] = a; red2[wid] = c; }

    __syncthreads();   // #1: prefix/suffix + halos + sum partials visible CTA-wide

    // ---- width-31 windows via prefix/suffix decomposition (log space) ----
    // F[i] = max e-logit[i..i+30]; B[j] = max s-logit[j-30..j]
    const float pe30 = __shfl_sync(0xffffffffu, pe, 30);
    const float ss1  = __shfl_sync(0xffffffffu, ssx, 1);
    float F, Bv;
    if (lane == 0)       F = pe30;
    else if (lane == 1)  F = se_;
    else                 F = fmaxf(se_, pfx_e[t + 30]);
    if (lane == 31)      Bv = ss1;
    else if (lane == 30) Bv = ps_;
    else                 Bv = fmaxf(ps_, sfx_s[t + 2]);

    // ---- log-space scores + warp argmax (dual, first-index tie-break) ----
    float bsv = sl + F;  int bsi = col;
    float bev = el + Bv; int bei = col;
    #pragma unroll
    for (int o = 16; o; o >>= 1) {
        float ov = __shfl_xor_sync(0xffffffffu, bsv, o);
        int   oi = __shfl_xor_sync(0xffffffffu, bsi, o);
        if (ov > bsv || (ov == bsv && oi < bsi)) { bsv = ov; bsi = oi; }
        float ov2 = __shfl_xor_sync(0xffffffffu, bev, o);
        int   oi2 = __shfl_xor_sync(0xffffffffu, bei, o);
        if (ov2 > bev || (ov2 == bev && oi2 < bei)) { bev = ov2; bei = oi2; }
    }
    if (lane == 0) { wav[wid] = bsv; wai[wid] = bsi; wav2[wid] = bev; wai2[wid] = bei; }

    __syncthreads();   // #2: warp partials visible

    // ---- parallel final reductions + remote pushes (all BEFORE the single cluster sync) ----
    if (wid == 0) {
        float aa = (lane < 16) ? red[lane]  : 0.f;
        float cc = (lane < 16) ? red2[lane] : 0.f;
        #pragma unroll
        for (int o = 8; o; o >>= 1) {
            aa += __shfl_xor_sync(0xffffffffu, aa, o);
            cc += __shfl_xor_sync(0xffffffffu, cc, o);
        }
        if (lane < 8)        st_remote_f32(&s_parts[rank], (unsigned int)lane, aa);
        else if (lane < 16)  st_remote_f32(&e_parts[rank], (unsigned int)(lane - 8), cc);
    } else if (wid == 1) {
        float v1 = (lane < 16) ? wav[lane] : -CUDART_INF_F;
        int   i1 = (lane < 16) ? wai[lane] : 0x7fffffff;
        #pragma unroll
        for (int o = 8; o; o >>= 1) {
            float ov = __shfl_xor_sync(0xffffffffu, v1, o);
            int   oi = __shfl_xor_sync(0xffffffffu, i1, o);
            if (ov > v1 || (ov == v1 && oi < i1)) { v1 = ov; i1 = oi; }
        }
        if (lane == 0) { st_remote_f32(&wsv[rank], 0u, v1); st_remote_s32(&wsi[rank], 0u, i1); }
    } else if (wid == 2) {
        float v2 = (lane < 16) ? wav2[lane] : -CUDART_INF_F;
        int   i2 = (lane < 16) ? wai2[lane] : 0x7fffffff;
        #pragma unroll
        for (int o = 8; o; o >>= 1) {
            float ov = __shfl_xor_sync(0xffffffffu, v2, o);
            int   oi = __shfl_xor_sync(0xffffffffu, i2, o);
            if (ov > v2 || (ov == v2 && oi < i2)) { v2 = ov; i2 = oi; }
        }
        if (lane == 0) { st_remote_f32(&wev[rank], 0u, v2); st_remote_s32(&wei[rank], 0u, i2); }
    }

    CLUSTER_SYNC();   // the ONLY cluster sync

    // ---- probs: every warp redundantly computes global inv-sums, then STG ----
    {
        float v = (lane < 8) ? s_parts[lane] : ((lane < 16) ? e_parts[lane - 8] : 0.f);
        v += __shfl_xor_sync(0xffffffffu, v, 4);
        v += __shfl_xor_sync(0xffffffffu, v, 2);
        v += __shfl_xor_sync(0xffffffffu, v, 1);
        const float inv_s = __frcp_rn(__shfl_sync(0xffffffffu, v, 0));
        const float inv_e = __frcp_rn(__shfl_sync(0xffffffffu, v, 8));
        out[row * SEQ + col]               = sv * inv_s;
        out[BATCH * SEQ + row * SEQ + col] = ev * inv_e;
    }

    // ---- rank 0 reduces the 8 cluster winners ----
    if (rank == 0 && wid == 0) {
        float v1 = (lane < 8) ? wsv[lane] : -CUDART_INF_F;
        int   i1 = (lane < 8) ? wsi[lane] : 0x7fffffff;
        float v2 = (lane < 8) ? wev[lane] : -CUDART_INF_F;
        int   i2 = (lane < 8) ? wei[lane] : 0x7fffffff;
        #pragma unroll
        for (int o = 4; o; o >>= 1) {
            float ov = __shfl_xor_sync(0xffffffffu, v1, o);
            int   oi = __shfl_xor_sync(0xffffffffu, i1, o);
            if (ov > v1 || (ov == v1 && oi < i1)) { v1 = ov; i1 = oi; }
            float ov2 = __shfl_xor_sync(0xffffffffu, v2, o);
            int   oi2 = __shfl_xor_sync(0xffffffffu, i2, o);
            if (ov2 > v2 || (ov2 == v2 && oi2 < i2)) { v2 = ov2; i2 = oi2; }
        }
        if (lane == 0) {
            out[2 * BATCH * SEQ + row]         = (float)i1;
            out[2 * BATCH * SEQ + BATCH + row] = (float)i2;
        }
    }
}

extern "C" void kernel_launch(void* const* d_in, const int* in_sizes, int n_in,
                              void* d_out, int out_size) {
    const float* start_logits = (const float*)d_in[0];
    const float* end_logits   = (const float*)d_in[1];
    float* out = (float*)d_out;
    pred_head_cluster<<<BATCH * RANKS, NTC>>>(start_logits, end_logits, out);
}